// round 1
// baseline (speedup 1.0000x reference)
#include <cuda_runtime.h>
#include <math.h>

#ifndef M_PI
#define M_PI 3.14159265358979323846
#endif

#define Bb 8
#define Hh 160
#define Ww 180
#define Cc 32
#define NPIX (Hh*Ww)          /* 28800 */
#define NIMG (Bb*NPIX)        /* 230400 */
#define NFEAT (Bb*Cc*NPIX)    /* 7372800 */
#define DELTA 0.01f

/* ------------------------- scratch (device globals) ------------------------- */
__device__ float2 g_x1[NIMG], g_x2[NIMG];
__device__ float2 g_c1[NIMG], g_c2[NIMG];
__device__ float2 g_ta[NIMG], g_tb[NIMG], g_gf[NIMG], g_gr[NIMG];
__device__ float2 g_act0[NFEAT], g_act1[NFEAT], g_act2[NFEAT];
__device__ float2 g_fb0[NFEAT], g_fb1[NFEAT];
__device__ float2 g_MW[Ww*Ww], g_MWi[Ww*Ww];   /* W-dim DFT (fwd / inv*1/W), symmetric */
__device__ float2 g_MH[Hh*Hh], g_MHi[Hh*Hh];   /* H-dim DFT */

/* ------------------------------- device math ------------------------------- */
__device__ __forceinline__ float actf(float x){
    if (fabsf(x) > DELTA) return x > 0.f ? x : 0.f;
    return x*x*(1.f/(4.f*DELTA)) + 0.5f*x + DELTA*0.25f;
}
__device__ __forceinline__ float actd(float x){
    if (fabsf(x) > DELTA) return x > 0.f ? 1.f : 0.f;
    return x*(1.f/(2.f*DELTA)) + 0.5f;
}

/* ------------------------------ setup kernels ------------------------------ */
__global__ void k_init_dft(){
    int i = blockIdx.x*blockDim.x + threadIdx.x;
    if (i < Ww*Ww){
        int u = i / Ww, w = i % Ww;
        int t = (u*w) % Ww;
        double ang = -2.0*M_PI*(double)t/(double)Ww;
        double s, c; sincos(ang, &s, &c);
        g_MW[i]  = make_float2((float)c, (float)s);
        g_MWi[i] = make_float2((float)(c/(double)Ww), (float)(-s/(double)Ww));
    }
    if (i < Hh*Hh){
        int u = i / Hh, h = i % Hh;
        int t = (u*h) % Hh;
        double ang = -2.0*M_PI*(double)t/(double)Hh;
        double s, c; sincos(ang, &s, &c);
        g_MH[i]  = make_float2((float)c, (float)s);
        g_MHi[i] = make_float2((float)(c/(double)Hh), (float)(-s/(double)Hh));
    }
}

__global__ void k_pack(const float* __restrict__ s, float2* __restrict__ d){
    int i = blockIdx.x*blockDim.x + threadIdx.x;
    if (i >= NIMG) return;
    int b = i / NPIX, p = i % NPIX;
    d[i] = make_float2(s[(size_t)(b*2+0)*NPIX + p], s[(size_t)(b*2+1)*NPIX + p]);
}

__global__ void k_maskk(const float* __restrict__ k, const float* __restrict__ mask,
                        float2* __restrict__ d){
    int i = blockIdx.x*blockDim.x + threadIdx.x;
    if (i >= NIMG) return;
    int b = i / NPIX, p = i % NPIX;
    float m = mask[p];
    d[i] = make_float2(m*k[(size_t)(b*2+0)*NPIX + p], m*k[(size_t)(b*2+1)*NPIX + p]);
}

/* ------------------------------- DFT kernels ------------------------------- */
/* transform along W: out[b,h,u] = sum_w in[b,h,w] * M[w*Ww+u]  (M symmetric) */
__global__ void k_dft_row(const float2* __restrict__ in, float2* __restrict__ out,
                          const float2* __restrict__ M){
    __shared__ float2 srow[Ww];
    int bh = blockIdx.x;
    int u  = threadIdx.x;          /* blockDim.x == Ww */
    srow[u] = in[(size_t)bh*Ww + u];
    __syncthreads();
    float sr = 0.f, si = 0.f;
    #pragma unroll 4
    for (int w = 0; w < Ww; w++){
        float2 m = M[w*Ww + u];
        float2 x = srow[w];
        sr = fmaf(x.x, m.x, sr); sr = fmaf(-x.y, m.y, sr);
        si = fmaf(x.x, m.y, si); si = fmaf( x.y, m.x, si);
    }
    out[(size_t)bh*Ww + u] = make_float2(sr, si);
}

/* transform along H: out[b,u,w] = sum_h in[b,h,w] * M[u*Hh+h] */
__global__ void k_dft_col(const float2* __restrict__ in, float2* __restrict__ out,
                          const float2* __restrict__ M){
    __shared__ float2 smrow[Hh];
    int u = blockIdx.x, b = blockIdx.y;
    int w = threadIdx.x;           /* blockDim.x == Ww */
    for (int h = threadIdx.x; h < Hh; h += blockDim.x) smrow[h] = M[u*Hh + h];
    __syncthreads();
    const float2* ip = in + (size_t)b*NPIX;
    float sr = 0.f, si = 0.f;
    #pragma unroll 4
    for (int h = 0; h < Hh; h++){
        float2 x = ip[h*Ww + w];
        float2 m = smrow[h];
        sr = fmaf(x.x, m.x, sr); sr = fmaf(-x.y, m.y, sr);
        si = fmaf(x.x, m.y, si); si = fmaf( x.y, m.x, si);
    }
    out[(size_t)b*NPIX + u*Ww + w] = make_float2(sr, si);
}

__global__ void k_mask2(float2* __restrict__ g, const float* __restrict__ mask){
    int i = blockIdx.x*blockDim.x + threadIdx.x;
    if (i >= NIMG) return;
    int p = i % NPIX;
    float m = mask[p]; m *= m;
    float2 v = g[i];
    g[i] = make_float2(v.x*m, v.y*m);
}

/* ----------------------------- complex conv 3x3 ----------------------------- */
/* fwd:  weights (Cout,Cs,3,3);  out[o] = sum_c w[o,c,ky,kx] * in[c, y+ky-1, x+kx-1]
   tr:   weights (Cs,Cout,3,3);  out[o] = sum_c w[c,o,2-ky,2-kx] * in[c, y+ky-1, x+kx-1] */
__global__ void k_cconv(const float2* __restrict__ in,
                        const float* __restrict__ wr, const float* __restrict__ wi,
                        float2* __restrict__ out,
                        int Cs, int Cout, int transposed, int doAct){
    extern __shared__ float sw[];
    float* swr = sw;
    float* swi = sw + Cs*9;
    int o = blockIdx.y, b = blockIdx.z;

    for (int t = threadIdx.x; t < Cs*9; t += blockDim.x){
        int c = t / 9, k = t % 9, ky = k/3, kx = k%3;
        int widx = transposed ? ((c*Cout + o)*9 + (2-ky)*3 + (2-kx))
                              : ((o*Cs + c)*9 + k);
        swr[t] = wr[widx];
        swi[t] = wi[widx];
    }
    __syncthreads();

    int p = blockIdx.x*blockDim.x + threadIdx.x;
    if (p >= NPIX) return;
    int h = p / Ww, w = p % Ww;

    float sr = 0.f, si = 0.f;
    for (int c = 0; c < Cs; c++){
        const float2* ip = in + ((size_t)b*Cs + c)*NPIX;
        const float* pwr = swr + c*9;
        const float* pwi = swi + c*9;
        #pragma unroll
        for (int ky = 0; ky < 3; ky++){
            int iy = h + ky - 1;
            if (iy < 0 || iy >= Hh) continue;
            const float2* rp = ip + iy*Ww;
            #pragma unroll
            for (int kx = 0; kx < 3; kx++){
                int ix = w + kx - 1;
                if (ix < 0 || ix >= Ww) continue;
                float2 xv = rp[ix];
                float a = pwr[ky*3+kx], bq = pwi[ky*3+kx];
                sr = fmaf(xv.x, a,  sr); sr = fmaf(-xv.y, bq, sr);
                si = fmaf(xv.x, bq, si); si = fmaf( xv.y, a,  si);
            }
        }
    }
    if (doAct){ sr = actf(sr); si = actf(si); }
    out[((size_t)b*Cout + o)*NPIX + p] = make_float2(sr, si);
}

/* ------------------------- threshold / normalize --------------------------- */
__global__ void k_thresh(const float2* __restrict__ in, float2* __restrict__ out,
                         const float* __restrict__ thrp){
    int p = blockIdx.x*blockDim.x + threadIdx.x;
    int b = blockIdx.y;
    if (p >= NPIX) return;
    float thr = thrp[0];      /* GAMMA = 1 */
    const float2* ip = in + (size_t)b*Cc*NPIX + p;
    float nrm = 0.f;
    #pragma unroll 8
    for (int c = 0; c < Cc; c++){
        float2 v = ip[(size_t)c*NPIX];
        nrm = fmaf(v.x, v.x, nrm);
        nrm = fmaf(v.y, v.y, nrm);
    }
    nrm = sqrtf(nrm);
    float denom = (nrm > thr) ? fmaxf(nrm, 1e-12f) : thr;
    float inv = 1.f/denom;
    float2* op = out + (size_t)b*Cc*NPIX + p;
    #pragma unroll 8
    for (int c = 0; c < Cc; c++){
        float2 v = ip[(size_t)c*NPIX];
        op[(size_t)c*NPIX] = make_float2(v.x*inv, v.y*inv);
    }
}

/* ---------------- complex multiply by activation derivative ---------------- */
__global__ void k_mulder(float2* __restrict__ g, const float2* __restrict__ act){
    int i = blockIdx.x*blockDim.x + threadIdx.x;
    if (i >= NFEAT) return;
    float2 a = act[i];
    float dr = actd(a.x), di = actd(a.y);
    float2 v = g[i];
    g[i] = make_float2(v.x*dr - v.y*di, v.x*di + v.y*dr);
}

/* --------------------------------- update ---------------------------------- */
__global__ void k_update(float2* __restrict__ x, const float2* __restrict__ gf,
                         const float2* __restrict__ cc, const float2* __restrict__ gr,
                         const float* __restrict__ al, const float* __restrict__ be, int ph){
    int i = blockIdx.x*blockDim.x + threadIdx.x;
    if (i >= NIMG) return;
    float a = al[ph], b = be[ph];
    float2 xv = x[i], f = gf[i], c = cc[i], r = gr[i];
    xv.x -= a*(f.x - c.x) + b*r.x;
    xv.y -= a*(f.y - c.y) + b*r.y;
    x[i] = xv;
}

__global__ void k_out(const float2* __restrict__ x1, const float2* __restrict__ x2,
                      float* __restrict__ o){
    int i = blockIdx.x*blockDim.x + threadIdx.x;
    if (i >= NIMG) return;
    int b = i / NPIX, p = i % NPIX;
    size_t base = (size_t)b*4*NPIX + p;
    o[base + 0*NPIX] = x1[i].x;
    o[base + 1*NPIX] = x1[i].y;
    o[base + 2*NPIX] = x2[i].x;
    o[base + 3*NPIX] = x2[i].y;
}

/* --------------------------------- launch ---------------------------------- */
static inline float2* symaddr(const void* sym){
    void* p = nullptr;
    cudaGetSymbolAddress(&p, sym);
    return (float2*)p;
}

extern "C" void kernel_launch(void* const* d_in, const int* in_sizes, int n_in,
                              void* d_out, int out_size){
    const float* x1in  = (const float*)d_in[0];
    const float* x2in  = (const float*)d_in[1];
    const float* k1in  = (const float*)d_in[2];
    const float* k2in  = (const float*)d_in[3];
    const float* mask  = (const float*)d_in[4];
    /* convsA: 5..12 (1r,1i,2r,2i,3r,3i,4r,4i), convsB: 13..20 */
    const float* thr1  = (const float*)d_in[21];
    const float* thr2  = (const float*)d_in[22];
    const float* al1   = (const float*)d_in[23];
    const float* al2   = (const float*)d_in[24];
    const float* be1   = (const float*)d_in[25];
    const float* be2   = (const float*)d_in[26];

    float2* X1  = symaddr(g_x1);   float2* X2  = symaddr(g_x2);
    float2* C1  = symaddr(g_c1);   float2* C2  = symaddr(g_c2);
    float2* TA  = symaddr(g_ta);   float2* TB  = symaddr(g_tb);
    float2* GF  = symaddr(g_gf);   float2* GR  = symaddr(g_gr);
    float2* A0  = symaddr(g_act0); float2* A1  = symaddr(g_act1); float2* A2 = symaddr(g_act2);
    float2* F0  = symaddr(g_fb0);  float2* F1  = symaddr(g_fb1);
    float2* MW  = symaddr(g_MW);   float2* MWi = symaddr(g_MWi);
    float2* MH  = symaddr(g_MH);   float2* MHi = symaddr(g_MHi);

    const int TPB = 256;
    const int gIMG  = (NIMG  + TPB - 1)/TPB;
    const int gFEAT = (NFEAT + TPB - 1)/TPB;
    const int gPIX  = (NPIX  + TPB - 1)/TPB;
    dim3 gridConv32(gPIX, 32, Bb);
    dim3 gridConv1 (gPIX, 1,  Bb);
    dim3 gridThr   (gPIX, Bb);
    dim3 gridCol   (Hh, Bb);
    const int smemW32 = 2*32*9*sizeof(float);
    const int smemW1  = 2*1*9*sizeof(float);

    /* setup */
    k_init_dft<<<(Ww*Ww + TPB - 1)/TPB, TPB>>>();
    k_pack<<<gIMG, TPB>>>(x1in, X1);
    k_pack<<<gIMG, TPB>>>(x2in, X2);
    /* constant term c = IFFT2(mask * k) per stream */
    k_maskk<<<gIMG, TPB>>>(k1in, mask, TA);
    k_dft_row<<<Bb*Hh, Ww>>>(TA, TB, MWi);
    k_dft_col<<<gridCol, Ww>>>(TB, C1, MHi);
    k_maskk<<<gIMG, TPB>>>(k2in, mask, TA);
    k_dft_row<<<Bb*Hh, Ww>>>(TA, TB, MWi);
    k_dft_col<<<gridCol, Ww>>>(TB, C2, MHi);

    for (int ph = 0; ph < 3; ph++){
        for (int s = 0; s < 2; s++){
            float2* X   = s ? X2 : X1;
            float2* Cst = s ? C2 : C1;
            int wb = s ? 13 : 5;
            const float* w1r = (const float*)d_in[wb+0];
            const float* w1i = (const float*)d_in[wb+1];
            const float* w2r = (const float*)d_in[wb+2];
            const float* w2i = (const float*)d_in[wb+3];
            const float* w3r = (const float*)d_in[wb+4];
            const float* w3i = (const float*)d_in[wb+5];
            const float* w4r = (const float*)d_in[wb+6];
            const float* w4i = (const float*)d_in[wb+7];
            const float* thr = s ? thr2 : thr1;
            const float* al  = s ? al2  : al1;
            const float* be  = s ? be2  : be1;

            /* grad_f (minus constant term): GF = IFFT2(mask^2 * FFT2(X)) */
            k_dft_row<<<Bb*Hh, Ww>>>(X,  TA, MW);
            k_dft_col<<<gridCol, Ww>>>(TA, TB, MH);
            k_mask2<<<gIMG, TPB>>>(TB, mask);
            k_dft_row<<<Bb*Hh, Ww>>>(TB, TA, MWi);
            k_dft_col<<<gridCol, Ww>>>(TA, GF, MHi);

            /* grad_r */
            k_cconv<<<gridConv32, TPB, smemW1 >>>(X,  w1r, w1i, A0, 1,  32, 0, 1);
            k_cconv<<<gridConv32, TPB, smemW32>>>(A0, w2r, w2i, A1, 32, 32, 0, 1);
            k_cconv<<<gridConv32, TPB, smemW32>>>(A1, w3r, w3i, A2, 32, 32, 0, 1);
            k_cconv<<<gridConv32, TPB, smemW32>>>(A2, w4r, w4i, F0, 32, 32, 0, 0);
            k_thresh<<<gridThr, TPB>>>(F0, F1, thr);
            k_cconv<<<gridConv32, TPB, smemW32>>>(F1, w4r, w4i, F0, 32, 32, 1, 0);
            k_mulder<<<gFEAT, TPB>>>(F0, A2);
            k_cconv<<<gridConv32, TPB, smemW32>>>(F0, w3r, w3i, F1, 32, 32, 1, 0);
            k_mulder<<<gFEAT, TPB>>>(F1, A1);
            k_cconv<<<gridConv32, TPB, smemW32>>>(F1, w2r, w2i, F0, 32, 32, 1, 0);
            k_mulder<<<gFEAT, TPB>>>(F0, A0);
            k_cconv<<<gridConv1,  TPB, smemW32>>>(F0, w1r, w1i, GR, 32, 1, 1, 0);

            k_update<<<gIMG, TPB>>>(X, GF, Cst, GR, al, be, ph);
        }
    }
    k_out<<<gIMG, TPB>>>(X1, X2, (float*)d_out);
}

// round 2
// speedup vs baseline: 2.5258x; 2.5258x over previous
#include <cuda_runtime.h>
#include <math.h>

#ifndef M_PI
#define M_PI 3.14159265358979323846
#endif

#define Bb 8
#define Hh 160
#define Ww 180
#define Cc 32
#define NPIX (Hh*Ww)          /* 28800 */
#define NIMG (Bb*NPIX)        /* 230400 */
#define NFEAT (Bb*Cc*NPIX)    /* 7372800 */
#define DELTA 0.01f

/* ------------------------- scratch (device globals) ------------------------- */
__device__ float2 g_x1[NIMG], g_x2[NIMG];
__device__ float2 g_c1[NIMG], g_c2[NIMG];
__device__ float2 g_ta[NIMG], g_tb[NIMG], g_gf[NIMG], g_gr[NIMG];
__device__ float2 g_act0[NFEAT], g_act1[NFEAT], g_act2[NFEAT];
__device__ float2 g_fb0[NFEAT], g_fb1[NFEAT];
__device__ float2 g_MW[Ww*Ww], g_MWi[Ww*Ww];
__device__ float2 g_MH[Hh*Hh], g_MHi[Hh*Hh];

/* ------------------------------- device math ------------------------------- */
__device__ __forceinline__ float actf(float x){
    if (fabsf(x) > DELTA) return x > 0.f ? x : 0.f;
    return x*x*(1.f/(4.f*DELTA)) + 0.5f*x + DELTA*0.25f;
}
__device__ __forceinline__ float actd(float x){
    if (fabsf(x) > DELTA) return x > 0.f ? 1.f : 0.f;
    return x*(1.f/(2.f*DELTA)) + 0.5f;
}

__device__ __forceinline__ unsigned long long pk2(float lo, float hi){
    unsigned long long r;
    asm("mov.b64 %0, {%1, %2};" : "=l"(r) : "f"(lo), "f"(hi));
    return r;
}
__device__ __forceinline__ void upk2(unsigned long long v, float& lo, float& hi){
    asm("mov.b64 {%0, %1}, %2;" : "=f"(lo), "=f"(hi) : "l"(v));
}
__device__ __forceinline__ void fma2(unsigned long long& acc, unsigned long long a,
                                     unsigned long long b){
    asm("fma.rn.f32x2 %0, %1, %2, %0;" : "+l"(acc) : "l"(a), "l"(b));
}

/* ------------------------------ setup kernels ------------------------------ */
__global__ void k_init_dft(){
    int i = blockIdx.x*blockDim.x + threadIdx.x;
    if (i < Ww*Ww){
        int u = i / Ww, w = i % Ww;
        int t = (u*w) % Ww;
        double ang = -2.0*M_PI*(double)t/(double)Ww;
        double s, c; sincos(ang, &s, &c);
        g_MW[i]  = make_float2((float)c, (float)s);
        g_MWi[i] = make_float2((float)(c/(double)Ww), (float)(-s/(double)Ww));
    }
    if (i < Hh*Hh){
        int u = i / Hh, h = i % Hh;
        int t = (u*h) % Hh;
        double ang = -2.0*M_PI*(double)t/(double)Hh;
        double s, c; sincos(ang, &s, &c);
        g_MH[i]  = make_float2((float)c, (float)s);
        g_MHi[i] = make_float2((float)(c/(double)Hh), (float)(-s/(double)Hh));
    }
}

__global__ void k_pack(const float* __restrict__ s, float2* __restrict__ d){
    int i = blockIdx.x*blockDim.x + threadIdx.x;
    if (i >= NIMG) return;
    int b = i / NPIX, p = i % NPIX;
    d[i] = make_float2(s[(size_t)(b*2+0)*NPIX + p], s[(size_t)(b*2+1)*NPIX + p]);
}

__global__ void k_maskk(const float* __restrict__ k, const float* __restrict__ mask,
                        float2* __restrict__ d){
    int i = blockIdx.x*blockDim.x + threadIdx.x;
    if (i >= NIMG) return;
    int b = i / NPIX, p = i % NPIX;
    float m = mask[p];
    d[i] = make_float2(m*k[(size_t)(b*2+0)*NPIX + p], m*k[(size_t)(b*2+1)*NPIX + p]);
}

/* ------------------------------- DFT kernels ------------------------------- */
__global__ void k_dft_row(const float2* __restrict__ in, float2* __restrict__ out,
                          const float2* __restrict__ M){
    __shared__ float2 srow[Ww];
    int bh = blockIdx.x;
    int u  = threadIdx.x;
    srow[u] = in[(size_t)bh*Ww + u];
    __syncthreads();
    float sr = 0.f, si = 0.f;
    #pragma unroll 4
    for (int w = 0; w < Ww; w++){
        float2 m = M[w*Ww + u];
        float2 x = srow[w];
        sr = fmaf(x.x, m.x, sr); sr = fmaf(-x.y, m.y, sr);
        si = fmaf(x.x, m.y, si); si = fmaf( x.y, m.x, si);
    }
    out[(size_t)bh*Ww + u] = make_float2(sr, si);
}

__global__ void k_dft_col(const float2* __restrict__ in, float2* __restrict__ out,
                          const float2* __restrict__ M){
    __shared__ float2 smrow[Hh];
    int u = blockIdx.x, b = blockIdx.y;
    int w = threadIdx.x;
    for (int h = threadIdx.x; h < Hh; h += blockDim.x) smrow[h] = M[u*Hh + h];
    __syncthreads();
    const float2* ip = in + (size_t)b*NPIX;
    float sr = 0.f, si = 0.f;
    #pragma unroll 4
    for (int h = 0; h < Hh; h++){
        float2 x = ip[h*Ww + w];
        float2 m = smrow[h];
        sr = fmaf(x.x, m.x, sr); sr = fmaf(-x.y, m.y, sr);
        si = fmaf(x.x, m.y, si); si = fmaf( x.y, m.x, si);
    }
    out[(size_t)b*NPIX + u*Ww + w] = make_float2(sr, si);
}

__global__ void k_mask2(float2* __restrict__ g, const float* __restrict__ mask){
    int i = blockIdx.x*blockDim.x + threadIdx.x;
    if (i >= NIMG) return;
    int p = i % NPIX;
    float m = mask[p]; m *= m;
    float2 v = g[i];
    g[i] = make_float2(v.x*m, v.y*m);
}

/* ---------------- packed complex conv: all 32 outputs per thread ------------ */
/* EPI: 0 = none, 1 = smoothed-ReLU activation, 2 = complex-multiply by act-derivative */
template<int CS, int TRANS, int EPI>
__global__ void __launch_bounds__(256)
k_conv32(const float2* __restrict__ in,
         const float* __restrict__ wr, const float* __restrict__ wi,
         float2* __restrict__ out, const float2* __restrict__ act)
{
    extern __shared__ unsigned long long sw[];   /* [CS][9][32] packed (wr,wi) */
    const int b = blockIdx.y;

    for (int t = threadIdx.x; t < CS*9*32; t += 256){
        int o = t & 31; int tap = (t >> 5) % 9; int c = t/(32*9);
        int ky = tap/3, kx = tap%3;
        int widx = TRANS ? ((c*32 + o)*9 + (2-ky)*3 + (2-kx))
                         : ((o*CS + c)*9 + tap);
        sw[t] = pk2(wr[widx], wi[widx]);
    }
    __syncthreads();

    int p = blockIdx.x*256 + threadIdx.x;
    const bool pv = p < NPIX;
    const int pc = pv ? p : 0;
    const int h = pc / Ww, w = pc % Ww;

    unsigned long long a1[32], a2[32];
    #pragma unroll
    for (int o = 0; o < 32; o++){ a1[o] = 0ULL; a2[o] = 0ULL; }

    const float2* ip = in + (size_t)b*CS*NPIX + pc;
    for (int c = 0; c < CS; c++, ip += NPIX){
        #pragma unroll
        for (int tap = 0; tap < 9; tap++){
            const int ky = tap/3, kx = tap%3;
            bool v = pv && (ky != 0 || h > 0) && (ky != 2 || h < Hh-1)
                        && (kx != 0 || w > 0) && (kx != 2 || w < Ww-1);
            float2 x = v ? ip[(ky-1)*Ww + (kx-1)] : make_float2(0.f, 0.f);
            unsigned long long xr = pk2(x.x, x.x);
            unsigned long long xi = pk2(x.y, x.y);
            const ulonglong2* wp = (const ulonglong2*)(sw + (c*9 + tap)*32);
            #pragma unroll
            for (int o2 = 0; o2 < 16; o2++){
                ulonglong2 wv = wp[o2];
                fma2(a1[2*o2  ], xr, wv.x);
                fma2(a2[2*o2  ], xi, wv.x);
                fma2(a1[2*o2+1], xr, wv.y);
                fma2(a2[2*o2+1], xi, wv.y);
            }
        }
    }
    if (!pv) return;
    float2* op = out + (size_t)b*32*NPIX + p;
    const float2* ap = act + (size_t)b*32*NPIX + p;
    #pragma unroll
    for (int o = 0; o < 32; o++){
        float r1l, r1h, r2l, r2h;
        upk2(a1[o], r1l, r1h);
        upk2(a2[o], r2l, r2h);
        float re = r1l - r2h;
        float im = r1h + r2l;
        if (EPI == 1){ re = actf(re); im = actf(im); }
        if (EPI == 2){
            float2 a = ap[(size_t)o*NPIX];
            float dr = actd(a.x), di = actd(a.y);
            float nre = re*dr - im*di;
            im = re*di + im*dr;
            re = nre;
        }
        op[(size_t)o*NPIX] = make_float2(re, im);
    }
}

/* ----------------- scalar conv for the 32->1 transposed tail ---------------- */
__global__ void k_cconv_t1(const float2* __restrict__ in,
                           const float* __restrict__ wr, const float* __restrict__ wi,
                           float2* __restrict__ out)
{
    __shared__ float swr[32*9], swi[32*9];
    int b = blockIdx.z;
    for (int t = threadIdx.x; t < 32*9; t += blockDim.x){
        int c = t / 9, k = t % 9, ky = k/3, kx = k%3;
        int widx = (c*1 + 0)*9 + (2-ky)*3 + (2-kx);
        swr[t] = wr[widx];
        swi[t] = wi[widx];
    }
    __syncthreads();
    int p = blockIdx.x*blockDim.x + threadIdx.x;
    if (p >= NPIX) return;
    int h = p / Ww, w = p % Ww;
    float sr = 0.f, si = 0.f;
    for (int c = 0; c < 32; c++){
        const float2* ip = in + ((size_t)b*32 + c)*NPIX;
        const float* pwr = swr + c*9;
        const float* pwi = swi + c*9;
        #pragma unroll
        for (int ky = 0; ky < 3; ky++){
            int iy = h + ky - 1;
            if (iy < 0 || iy >= Hh) continue;
            const float2* rp = ip + iy*Ww;
            #pragma unroll
            for (int kx = 0; kx < 3; kx++){
                int ix = w + kx - 1;
                if (ix < 0 || ix >= Ww) continue;
                float2 xv = rp[ix];
                float a = pwr[ky*3+kx], bq = pwi[ky*3+kx];
                sr = fmaf(xv.x, a,  sr); sr = fmaf(-xv.y, bq, sr);
                si = fmaf(xv.x, bq, si); si = fmaf( xv.y, a,  si);
            }
        }
    }
    out[(size_t)b*NPIX + p] = make_float2(sr, si);
}

/* ------------------------- threshold / normalize --------------------------- */
__global__ void k_thresh(const float2* __restrict__ in, float2* __restrict__ out,
                         const float* __restrict__ thrp){
    int p = blockIdx.x*blockDim.x + threadIdx.x;
    int b = blockIdx.y;
    if (p >= NPIX) return;
    float thr = thrp[0];
    const float2* ip = in + (size_t)b*Cc*NPIX + p;
    float nrm = 0.f;
    #pragma unroll 8
    for (int c = 0; c < Cc; c++){
        float2 v = ip[(size_t)c*NPIX];
        nrm = fmaf(v.x, v.x, nrm);
        nrm = fmaf(v.y, v.y, nrm);
    }
    nrm = sqrtf(nrm);
    float denom = (nrm > thr) ? fmaxf(nrm, 1e-12f) : thr;
    float inv = 1.f/denom;
    float2* op = out + (size_t)b*Cc*NPIX + p;
    #pragma unroll 8
    for (int c = 0; c < Cc; c++){
        float2 v = ip[(size_t)c*NPIX];
        op[(size_t)c*NPIX] = make_float2(v.x*inv, v.y*inv);
    }
}

/* --------------------------------- update ---------------------------------- */
__global__ void k_update(float2* __restrict__ x, const float2* __restrict__ gf,
                         const float2* __restrict__ cc, const float2* __restrict__ gr,
                         const float* __restrict__ al, const float* __restrict__ be, int ph){
    int i = blockIdx.x*blockDim.x + threadIdx.x;
    if (i >= NIMG) return;
    float a = al[ph], b = be[ph];
    float2 xv = x[i], f = gf[i], c = cc[i], r = gr[i];
    xv.x -= a*(f.x - c.x) + b*r.x;
    xv.y -= a*(f.y - c.y) + b*r.y;
    x[i] = xv;
}

__global__ void k_out(const float2* __restrict__ x1, const float2* __restrict__ x2,
                      float* __restrict__ o){
    int i = blockIdx.x*blockDim.x + threadIdx.x;
    if (i >= NIMG) return;
    int b = i / NPIX, p = i % NPIX;
    size_t base = (size_t)b*4*NPIX + p;
    o[base + 0*NPIX] = x1[i].x;
    o[base + 1*NPIX] = x1[i].y;
    o[base + 2*NPIX] = x2[i].x;
    o[base + 3*NPIX] = x2[i].y;
}

/* --------------------------------- launch ---------------------------------- */
static inline float2* symaddr(const void* sym){
    void* p = nullptr;
    cudaGetSymbolAddress(&p, sym);
    return (float2*)p;
}

extern "C" void kernel_launch(void* const* d_in, const int* in_sizes, int n_in,
                              void* d_out, int out_size){
    const float* x1in  = (const float*)d_in[0];
    const float* x2in  = (const float*)d_in[1];
    const float* k1in  = (const float*)d_in[2];
    const float* k2in  = (const float*)d_in[3];
    const float* mask  = (const float*)d_in[4];
    const float* thr1  = (const float*)d_in[21];
    const float* thr2  = (const float*)d_in[22];
    const float* al1   = (const float*)d_in[23];
    const float* al2   = (const float*)d_in[24];
    const float* be1   = (const float*)d_in[25];
    const float* be2   = (const float*)d_in[26];

    float2* X1  = symaddr(g_x1);   float2* X2  = symaddr(g_x2);
    float2* C1  = symaddr(g_c1);   float2* C2  = symaddr(g_c2);
    float2* TA  = symaddr(g_ta);   float2* TB  = symaddr(g_tb);
    float2* GF  = symaddr(g_gf);   float2* GR  = symaddr(g_gr);
    float2* A0  = symaddr(g_act0); float2* A1  = symaddr(g_act1); float2* A2 = symaddr(g_act2);
    float2* F0  = symaddr(g_fb0);  float2* F1  = symaddr(g_fb1);
    float2* MW  = symaddr(g_MW);   float2* MWi = symaddr(g_MWi);
    float2* MH  = symaddr(g_MH);   float2* MHi = symaddr(g_MHi);

    const int TPB = 256;
    const int gIMG  = (NIMG  + TPB - 1)/TPB;
    const int gPIX  = (NPIX  + TPB - 1)/TPB;     /* 113 */
    dim3 gridConv(gPIX, Bb);
    dim3 gridT1  (gPIX, 1, Bb);
    dim3 gridThr (gPIX, Bb);
    dim3 gridCol (Hh, Bb);
    const int SMEM_H = 32*9*32*8;    /* 73728 B */
    const int SMEM_1 = 1*9*32*8;     /* 2304 B  */

    /* opt-in to >48KB dynamic smem (idempotent host calls) */
    cudaFuncSetAttribute(k_conv32<32,0,1>, cudaFuncAttributeMaxDynamicSharedMemorySize, SMEM_H);
    cudaFuncSetAttribute(k_conv32<32,0,0>, cudaFuncAttributeMaxDynamicSharedMemorySize, SMEM_H);
    cudaFuncSetAttribute(k_conv32<32,1,2>, cudaFuncAttributeMaxDynamicSharedMemorySize, SMEM_H);

    /* setup */
    k_init_dft<<<(Ww*Ww + TPB - 1)/TPB, TPB>>>();
    k_pack<<<gIMG, TPB>>>(x1in, X1);
    k_pack<<<gIMG, TPB>>>(x2in, X2);
    k_maskk<<<gIMG, TPB>>>(k1in, mask, TA);
    k_dft_row<<<Bb*Hh, Ww>>>(TA, TB, MWi);
    k_dft_col<<<gridCol, Ww>>>(TB, C1, MHi);
    k_maskk<<<gIMG, TPB>>>(k2in, mask, TA);
    k_dft_row<<<Bb*Hh, Ww>>>(TA, TB, MWi);
    k_dft_col<<<gridCol, Ww>>>(TB, C2, MHi);

    for (int ph = 0; ph < 3; ph++){
        for (int s = 0; s < 2; s++){
            float2* X   = s ? X2 : X1;
            float2* Cst = s ? C2 : C1;
            int wb = s ? 13 : 5;
            const float* w1r = (const float*)d_in[wb+0];
            const float* w1i = (const float*)d_in[wb+1];
            const float* w2r = (const float*)d_in[wb+2];
            const float* w2i = (const float*)d_in[wb+3];
            const float* w3r = (const float*)d_in[wb+4];
            const float* w3i = (const float*)d_in[wb+5];
            const float* w4r = (const float*)d_in[wb+6];
            const float* w4i = (const float*)d_in[wb+7];
            const float* thr = s ? thr2 : thr1;
            const float* al  = s ? al2  : al1;
            const float* be  = s ? be2  : be1;

            /* grad_f (minus constant term): GF = IFFT2(mask^2 * FFT2(X)) */
            k_dft_row<<<Bb*Hh, Ww>>>(X,  TA, MW);
            k_dft_col<<<gridCol, Ww>>>(TA, TB, MH);
            k_mask2<<<gIMG, TPB>>>(TB, mask);
            k_dft_row<<<Bb*Hh, Ww>>>(TB, TA, MWi);
            k_dft_col<<<gridCol, Ww>>>(TA, GF, MHi);

            /* grad_r — forward chain (activation fused) */
            k_conv32<1, 0, 1><<<gridConv, TPB, SMEM_1>>>(X,  w1r, w1i, A0, nullptr);
            k_conv32<32,0, 1><<<gridConv, TPB, SMEM_H>>>(A0, w2r, w2i, A1, nullptr);
            k_conv32<32,0, 1><<<gridConv, TPB, SMEM_H>>>(A1, w3r, w3i, A2, nullptr);
            k_conv32<32,0, 0><<<gridConv, TPB, SMEM_H>>>(A2, w4r, w4i, F0, nullptr);
            k_thresh<<<gridThr, TPB>>>(F0, F1, thr);
            /* transposed chain (derivative complex-multiply fused) */
            k_conv32<32,1, 2><<<gridConv, TPB, SMEM_H>>>(F1, w4r, w4i, F0, A2);
            k_conv32<32,1, 2><<<gridConv, TPB, SMEM_H>>>(F0, w3r, w3i, F1, A1);
            k_conv32<32,1, 2><<<gridConv, TPB, SMEM_H>>>(F1, w2r, w2i, F0, A0);
            k_cconv_t1<<<gridT1, TPB>>>(F0, w1r, w1i, GR);

            k_update<<<gIMG, TPB>>>(X, GF, Cst, GR, al, be, ph);
        }
    }
    k_out<<<gIMG, TPB>>>(X1, X2, (float*)d_out);
}